// round 2
// baseline (speedup 1.0000x reference)
#include <cuda_runtime.h>
#include <math.h>

// Problem constants
#define NB   16
#define NC   512
#define NC1  256
#define NHW  4096

// Scratch (device globals; no allocation allowed)
__device__ float g_Gp[2ull * NB * NC * NC];    // split-K partial Gram, 32 MB
__device__ float g_G [ (size_t)NB * NC * NC];  // Gram, 16 MB
__device__ float g_s [ NB * NC ];              // row sums of k
__device__ float g_E [ (size_t)NB * NC1 * NC]; // energy, 8 MB
__device__ float g_M [ (size_t)NB * NC1 * NC]; // gamma*attn + W, 8 MB

// ---------------------------------------------------------------------------
// Row sums: s[b][c] = sum_n x[b][c][n]
// ---------------------------------------------------------------------------
__global__ void rowsum_kernel(const float* __restrict__ x) {
    int row = blockIdx.x;                 // b*512 + c, 0..8191
    int t = threadIdx.x;                  // 128 threads
    const float4* xr = (const float4*)(x + (size_t)row * NHW);
    float sum = 0.f;
#pragma unroll
    for (int i = 0; i < 8; i++) {
        float4 v = xr[i * 128 + t];
        sum += (v.x + v.y) + (v.z + v.w);
    }
    __shared__ float red[128];
    red[t] = sum; __syncthreads();
    for (int s = 64; s > 0; s >>= 1) {
        if (t < s) red[t] += red[t + s];
        __syncthreads();
    }
    if (t == 0) g_s[row] = red[0];
}

// ---------------------------------------------------------------------------
// Gram partials: Gp[kc][b] = k[:, kc*2048:(kc+1)*2048] @ same^T (triangle tiles)
// 128x128 tile, 256 threads, 8x8 per thread, BK=16
// ---------------------------------------------------------------------------
__global__ __launch_bounds__(256) void gram_kernel(const float* __restrict__ x) {
    int bx = blockIdx.x;
    int kc = bx & 1;                      // 2-way split-K
    int t2 = bx >> 1;
    int b = t2 / 10;
    int tri = t2 % 10;
    int bi = 0, rr = tri;
    while (rr >= 4 - bi) { rr -= 4 - bi; bi++; }
    int bj = bi + rr;                     // bi <= bj, 4x4 tile grid

    const float* A  = x + (size_t)b * NC * NHW + (size_t)(bi * 128) * NHW + kc * 2048;
    const float* Bp = x + (size_t)b * NC * NHW + (size_t)(bj * 128) * NHW + kc * 2048;

    __shared__ float As[16][132];
    __shared__ float Bs[16][132];

    int tid  = threadIdx.x;
    int lrow = tid >> 1;                  // 0..127
    int lk   = (tid & 1) * 8;             // 0 or 8
    int ty   = tid >> 4, tx = tid & 15;

    float acc[8][8];
#pragma unroll
    for (int u = 0; u < 8; u++)
#pragma unroll
        for (int v = 0; v < 8; v++) acc[u][v] = 0.f;

    for (int k0 = 0; k0 < 2048; k0 += 16) {
        float4 a0 = *(const float4*)(A  + lrow * NHW + k0 + lk);
        float4 a1 = *(const float4*)(A  + lrow * NHW + k0 + lk + 4);
        float4 b0 = *(const float4*)(Bp + lrow * NHW + k0 + lk);
        float4 b1 = *(const float4*)(Bp + lrow * NHW + k0 + lk + 4);
        __syncthreads();
        As[lk+0][lrow]=a0.x; As[lk+1][lrow]=a0.y; As[lk+2][lrow]=a0.z; As[lk+3][lrow]=a0.w;
        As[lk+4][lrow]=a1.x; As[lk+5][lrow]=a1.y; As[lk+6][lrow]=a1.z; As[lk+7][lrow]=a1.w;
        Bs[lk+0][lrow]=b0.x; Bs[lk+1][lrow]=b0.y; Bs[lk+2][lrow]=b0.z; Bs[lk+3][lrow]=b0.w;
        Bs[lk+4][lrow]=b1.x; Bs[lk+5][lrow]=b1.y; Bs[lk+6][lrow]=b1.z; Bs[lk+7][lrow]=b1.w;
        __syncthreads();
#pragma unroll
        for (int kk = 0; kk < 16; kk++) {
            float af[8], bf[8];
            *(float4*)&af[0] = *(const float4*)&As[kk][ty * 8];
            *(float4*)&af[4] = *(const float4*)&As[kk][ty * 8 + 4];
            *(float4*)&bf[0] = *(const float4*)&Bs[kk][tx * 8];
            *(float4*)&bf[4] = *(const float4*)&Bs[kk][tx * 8 + 4];
#pragma unroll
            for (int u = 0; u < 8; u++)
#pragma unroll
                for (int v = 0; v < 8; v++) acc[u][v] += af[u] * bf[v];
        }
    }

    float* Gp = g_Gp + (size_t)kc * NB * NC * NC + (size_t)b * NC * NC;
    int r0 = bi * 128 + ty * 8;
    int c0 = bj * 128 + tx * 8;
#pragma unroll
    for (int u = 0; u < 8; u++) {
        *(float4*)(Gp + (size_t)(r0 + u) * NC + c0)     = make_float4(acc[u][0], acc[u][1], acc[u][2], acc[u][3]);
        *(float4*)(Gp + (size_t)(r0 + u) * NC + c0 + 4) = make_float4(acc[u][4], acc[u][5], acc[u][6], acc[u][7]);
    }
    if (bi != bj) {
#pragma unroll
        for (int v = 0; v < 8; v++) {
            *(float4*)(Gp + (size_t)(c0 + v) * NC + r0)     = make_float4(acc[0][v], acc[1][v], acc[2][v], acc[3][v]);
            *(float4*)(Gp + (size_t)(c0 + v) * NC + r0 + 4) = make_float4(acc[4][v], acc[5][v], acc[6][v], acc[7][v]);
        }
    }
}

// ---------------------------------------------------------------------------
// Reduce 2 K-split partials into G (deterministic)
// ---------------------------------------------------------------------------
__global__ void greduce_kernel() {
    int idx = blockIdx.x * 256 + threadIdx.x;     // 0..1048575 float4s
    const size_t per = (size_t)NB * NC * NC / 4;  // float4s per partial
    const float4* p0 = (const float4*)g_Gp;
    float4 a = p0[idx], b = p0[per + idx];
    float4 r;
    r.x = a.x + b.x;
    r.y = a.y + b.y;
    r.z = a.z + b.z;
    r.w = a.w + b.w;
    ((float4*)g_G)[idx] = r;
}

// ---------------------------------------------------------------------------
// energy = (W @ G + bias * s^T) / 64        (uses G symmetry: read G rows)
// M=256, N=512, K=512; 128x128 tiles
// ---------------------------------------------------------------------------
__global__ __launch_bounds__(256) void energy_kernel(const float* __restrict__ W,
                                                     const float* __restrict__ bias) {
    int bx = blockIdx.x;
    int bn = bx & 3;
    int bm = (bx >> 2) & 1;
    int b  = bx >> 3;

    const float* A  = W + (size_t)(bm * 128) * NC;
    const float* Bp = g_G + (size_t)b * NC * NC + (size_t)(bn * 128) * NC;

    __shared__ float As[16][132];
    __shared__ float Bs[16][132];

    int tid  = threadIdx.x;
    int lrow = tid >> 1;
    int lk   = (tid & 1) * 8;
    int ty   = tid >> 4, tx = tid & 15;

    float acc[8][8];
#pragma unroll
    for (int u = 0; u < 8; u++)
#pragma unroll
        for (int v = 0; v < 8; v++) acc[u][v] = 0.f;

    for (int k0 = 0; k0 < NC; k0 += 16) {
        float4 a0 = *(const float4*)(A  + lrow * NC + k0 + lk);
        float4 a1 = *(const float4*)(A  + lrow * NC + k0 + lk + 4);
        float4 b0 = *(const float4*)(Bp + lrow * NC + k0 + lk);
        float4 b1 = *(const float4*)(Bp + lrow * NC + k0 + lk + 4);
        __syncthreads();
        As[lk+0][lrow]=a0.x; As[lk+1][lrow]=a0.y; As[lk+2][lrow]=a0.z; As[lk+3][lrow]=a0.w;
        As[lk+4][lrow]=a1.x; As[lk+5][lrow]=a1.y; As[lk+6][lrow]=a1.z; As[lk+7][lrow]=a1.w;
        Bs[lk+0][lrow]=b0.x; Bs[lk+1][lrow]=b0.y; Bs[lk+2][lrow]=b0.z; Bs[lk+3][lrow]=b0.w;
        Bs[lk+4][lrow]=b1.x; Bs[lk+5][lrow]=b1.y; Bs[lk+6][lrow]=b1.z; Bs[lk+7][lrow]=b1.w;
        __syncthreads();
#pragma unroll
        for (int kk = 0; kk < 16; kk++) {
            float af[8], bf[8];
            *(float4*)&af[0] = *(const float4*)&As[kk][ty * 8];
            *(float4*)&af[4] = *(const float4*)&As[kk][ty * 8 + 4];
            *(float4*)&bf[0] = *(const float4*)&Bs[kk][tx * 8];
            *(float4*)&bf[4] = *(const float4*)&Bs[kk][tx * 8 + 4];
#pragma unroll
            for (int u = 0; u < 8; u++)
#pragma unroll
                for (int v = 0; v < 8; v++) acc[u][v] += af[u] * bf[v];
        }
    }

    int r0 = bm * 128 + ty * 8;   // q
    int c0 = bn * 128 + tx * 8;   // j
    const float* sb = g_s + b * NC;
    float* E = g_E + (size_t)b * NC1 * NC;
    float sv[8];
#pragma unroll
    for (int v = 0; v < 8; v++) sv[v] = sb[c0 + v];
#pragma unroll
    for (int u = 0; u < 8; u++) {
        float bq = bias[r0 + u];
        float e[8];
#pragma unroll
        for (int v = 0; v < 8; v++) e[v] = (acc[u][v] + bq * sv[v]) * 0.015625f;
        *(float4*)(E + (size_t)(r0 + u) * NC + c0)     = make_float4(e[0], e[1], e[2], e[3]);
        *(float4*)(E + (size_t)(r0 + u) * NC + c0 + 4) = make_float4(e[4], e[5], e[6], e[7]);
    }
}

// ---------------------------------------------------------------------------
// M = gamma * softmax(E, axis=-1) + W        (one block per (b,q) row of 512)
// ---------------------------------------------------------------------------
__global__ void softmax_kernel(const float* __restrict__ W,
                               const float* __restrict__ gamma) {
    int bid = blockIdx.x;             // b*256 + q
    int q = bid & 255;
    int t = threadIdx.x;              // 128
    const float* Er = g_E + (size_t)bid * NC;
    float e[4];
#pragma unroll
    for (int i = 0; i < 4; i++) e[i] = Er[t + i * 128];
    float mx = fmaxf(fmaxf(e[0], e[1]), fmaxf(e[2], e[3]));

    __shared__ float red[128];
    red[t] = mx; __syncthreads();
    for (int s = 64; s > 0; s >>= 1) {
        if (t < s) red[t] = fmaxf(red[t], red[t + s]);
        __syncthreads();
    }
    mx = red[0];
    __syncthreads();

    float p[4], sum = 0.f;
#pragma unroll
    for (int i = 0; i < 4; i++) { p[i] = __expf(e[i] - mx); sum += p[i]; }
    red[t] = sum; __syncthreads();
    for (int s = 64; s > 0; s >>= 1) {
        if (t < s) red[t] += red[t + s];
        __syncthreads();
    }
    sum = red[0];

    float scale = gamma[0] / sum;
    float* Mr = g_M + (size_t)bid * NC;
    const float* Wr = W + (size_t)q * NC;
#pragma unroll
    for (int i = 0; i < 4; i++) Mr[t + i * 128] = p[i] * scale + Wr[t + i * 128];
}

// ---------------------------------------------------------------------------
// out = M @ k + bias     (M: 256x512 K-contig, k: 512x4096 N-contig)
// M=256, N=4096, K=512; 128x128 tiles
// ---------------------------------------------------------------------------
__global__ __launch_bounds__(256) void out_kernel(const float* __restrict__ x,
                                                  const float* __restrict__ bias,
                                                  float* __restrict__ out) {
    int bx = blockIdx.x;
    int bn = bx & 31;
    int bm = (bx >> 5) & 1;
    int b  = bx >> 6;

    const float* A  = g_M + ((size_t)b * NC1 + bm * 128) * NC;
    const float* Bp = x + (size_t)b * NC * NHW + bn * 128;

    __shared__ float As[16][132];
    __shared__ float Bs[16][132];

    int tid  = threadIdx.x;
    int lrow = tid >> 1;              // A tile row 0..127
    int lk   = (tid & 1) * 8;
    int krow = tid >> 4;              // B tile k-row 0..15
    int nc   = (tid & 15) * 8;        // B tile col 0..120
    int ty   = tid >> 4, tx = tid & 15;

    float acc[8][8];
#pragma unroll
    for (int u = 0; u < 8; u++)
#pragma unroll
        for (int v = 0; v < 8; v++) acc[u][v] = 0.f;

    for (int k0 = 0; k0 < NC; k0 += 16) {
        float4 a0 = *(const float4*)(A + lrow * NC + k0 + lk);
        float4 a1 = *(const float4*)(A + lrow * NC + k0 + lk + 4);
        float4 b0 = *(const float4*)(Bp + (size_t)(k0 + krow) * NHW + nc);
        float4 b1 = *(const float4*)(Bp + (size_t)(k0 + krow) * NHW + nc + 4);
        __syncthreads();
        As[lk+0][lrow]=a0.x; As[lk+1][lrow]=a0.y; As[lk+2][lrow]=a0.z; As[lk+3][lrow]=a0.w;
        As[lk+4][lrow]=a1.x; As[lk+5][lrow]=a1.y; As[lk+6][lrow]=a1.z; As[lk+7][lrow]=a1.w;
        *(float4*)&Bs[krow][nc]     = b0;
        *(float4*)&Bs[krow][nc + 4] = b1;
        __syncthreads();
#pragma unroll
        for (int kk = 0; kk < 16; kk++) {
            float af[8], bf[8];
            *(float4*)&af[0] = *(const float4*)&As[kk][ty * 8];
            *(float4*)&af[4] = *(const float4*)&As[kk][ty * 8 + 4];
            *(float4*)&bf[0] = *(const float4*)&Bs[kk][tx * 8];
            *(float4*)&bf[4] = *(const float4*)&Bs[kk][tx * 8 + 4];
#pragma unroll
            for (int u = 0; u < 8; u++)
#pragma unroll
                for (int v = 0; v < 8; v++) acc[u][v] += af[u] * bf[v];
        }
    }

    int r0 = bm * 128 + ty * 8;    // q
    int c0 = bn * 128 + tx * 8;    // n
#pragma unroll
    for (int u = 0; u < 8; u++) {
        float bq = bias[r0 + u];
        float* op = out + ((size_t)b * NC1 + r0 + u) * NHW + c0;
        *(float4*)(op)     = make_float4(acc[u][0] + bq, acc[u][1] + bq, acc[u][2] + bq, acc[u][3] + bq);
        *(float4*)(op + 4) = make_float4(acc[u][4] + bq, acc[u][5] + bq, acc[u][6] + bq, acc[u][7] + bq);
    }
}

// ---------------------------------------------------------------------------
extern "C" void kernel_launch(void* const* d_in, const int* in_sizes, int n_in,
                              void* d_out, int out_size) {
    const float *x = nullptr, *w = nullptr, *bias = nullptr, *gamma = nullptr;
    for (int i = 0; i < n_in; i++) {
        switch (in_sizes[i]) {
            case NB * NC * NHW: x     = (const float*)d_in[i]; break;   // 33554432
            case NC1 * NC:      w     = (const float*)d_in[i]; break;   // 131072
            case NC1:           bias  = (const float*)d_in[i]; break;   // 256
            case 1:             gamma = (const float*)d_in[i]; break;
        }
    }
    if (!x)     x     = (const float*)d_in[0];
    if (!w)     w     = (const float*)d_in[1];
    if (!bias)  bias  = (const float*)d_in[2];
    if (!gamma) gamma = (const float*)d_in[3];
    float* out = (float*)d_out;

    rowsum_kernel <<<NB * NC, 128>>>(x);
    gram_kernel   <<<NB * 10 * 2, 256>>>(x);
    greduce_kernel<<<4096, 256>>>();
    energy_kernel <<<NB * 8, 256>>>(w, bias);
    softmax_kernel<<<NB * NC1, 128>>>(w, gamma);
    out_kernel    <<<NB * 64, 256>>>(x, bias, out);
}

// round 6
// speedup vs baseline: 1.5986x; 1.5986x over previous
#include <cuda_runtime.h>
#include <cuda_bf16.h>
#include <cstdint>

#define NB   16
#define NC   512
#define NC1  256
#define NHW  4096

// ---------------- scratch (device globals; no allocation allowed) ----------
__device__ __nv_bfloat16 g_H [(size_t)NB * NC  * NHW];  // x hi, [b][c][hw]
__device__ __nv_bfloat16 g_L [(size_t)NB * NC  * NHW];  // x lo
__device__ __nv_bfloat16 g_HT[(size_t)NB * NHW * NC ];  // x hi, [b][hw][c]
__device__ __nv_bfloat16 g_LT[(size_t)NB * NHW * NC ];  // x lo transposed
__device__ __nv_bfloat16 g_Gh[(size_t)NB * NC  * NC ];  // (Gram/64) hi
__device__ __nv_bfloat16 g_Gl[(size_t)NB * NC  * NC ];  // (Gram/64) lo
__device__ float         g_E [(size_t)NB * NC1 * NC ];  // energy
__device__ __nv_bfloat16 g_Mh[(size_t)NB * NC1 * NC ];  // (gamma*attn+W) hi
__device__ __nv_bfloat16 g_Ml[(size_t)NB * NC1 * NC ];
__device__ __nv_bfloat16 g_Wh[NC1 * NC];
__device__ __nv_bfloat16 g_Wl[NC1 * NC];
__device__ float         g_s [NB * NC];                 // rowsum(x)/64

// ---------------- PTX helpers ----------------------------------------------
__device__ __forceinline__ uint32_t smem_to_u32(const void* p) {
    uint32_t a;
    asm("{ .reg .u64 t; cvta.to.shared.u64 t, %1; cvt.u32.u64 %0, t; }" : "=r"(a) : "l"(p));
    return a;
}
#define CP_ASYNC16(dst, src) \
    asm volatile("cp.async.cg.shared.global [%0], [%1], 16;" :: "r"(dst), "l"(src) : "memory")
#define CP_COMMIT() asm volatile("cp.async.commit_group;" ::: "memory")
#define CP_WAIT1()  asm volatile("cp.async.wait_group 1;" ::: "memory")
#define CP_WAIT0()  asm volatile("cp.async.wait_group 0;" ::: "memory")

#define LDMX4(r, addr) \
    asm volatile("ldmatrix.sync.aligned.m8n8.x4.shared.b16 {%0,%1,%2,%3}, [%4];" \
                 : "=r"((r)[0]), "=r"((r)[1]), "=r"((r)[2]), "=r"((r)[3]) : "r"(addr))

#define MMA_BF16(d, a, b0, b1) \
    asm volatile("mma.sync.aligned.m16n8k16.row.col.f32.bf16.bf16.f32 " \
                 "{%0,%1,%2,%3}, {%4,%5,%6,%7}, {%8,%9}, {%0,%1,%2,%3};" \
                 : "+f"((d)[0]), "+f"((d)[1]), "+f"((d)[2]), "+f"((d)[3]) \
                 : "r"((a)[0]), "r"((a)[1]), "r"((a)[2]), "r"((a)[3]), "r"(b0), "r"(b1))

// ---------------------------------------------------------------------------
// prep kernels
// ---------------------------------------------------------------------------
__global__ void wsplit_kernel(const float* __restrict__ w) {
    int i = blockIdx.x * 256 + threadIdx.x;
#pragma unroll
    for (int j = 0; j < 4; j++) {
        int idx = i * 4 + j;
        float v = w[idx];
        __nv_bfloat16 h = __float2bfloat16(v);
        g_Wh[idx] = h;
        g_Wl[idx] = __float2bfloat16(v - __bfloat162float(h));
    }
}

__global__ void rowsum_kernel(const float* __restrict__ x) {
    int row = blockIdx.x;                            // b*512 + c
    int t = threadIdx.x;                             // 128
    const float4* xr = (const float4*)(x + (size_t)row * NHW);
    float sum = 0.f;
#pragma unroll
    for (int i = 0; i < 8; i++) {
        float4 v = xr[i * 128 + t];
        sum += (v.x + v.y) + (v.z + v.w);
    }
    __shared__ float red[128];
    red[t] = sum; __syncthreads();
    for (int s = 64; s > 0; s >>= 1) { if (t < s) red[t] += red[t + s]; __syncthreads(); }
    if (t == 0) g_s[row] = red[0] * 0.015625f;
}

// x -> H/L ([b][c][hw]) and HT/LT ([b][hw][c]); tiles 32c x 128hw
__global__ __launch_bounds__(256) void convert_kernel(const float* __restrict__ x) {
    int bx = blockIdx.x;
    int hw_t = bx & 31;
    int c_t  = (bx >> 5) & 15;
    int b    = bx >> 9;
    int tid = threadIdx.x;
    const float* xp = x + ((size_t)b * NC + c_t * 32) * NHW + hw_t * 128;

    __shared__ __nv_bfloat16 sh[32][136];
    __shared__ __nv_bfloat16 sl[32][136];

#pragma unroll
    for (int i = 0; i < 16; i++) {
        int idx = tid + i * 256;
        int r = idx >> 7, col = idx & 127;
        float v = xp[(size_t)r * NHW + col];
        __nv_bfloat16 h = __float2bfloat16(v);
        __nv_bfloat16 l = __float2bfloat16(v - __bfloat162float(h));
        size_t go = ((size_t)b * NC + c_t * 32 + r) * NHW + hw_t * 128 + col;
        g_H[go] = h; g_L[go] = l;
        sh[r][col] = h; sl[r][col] = l;
    }
    __syncthreads();
#pragma unroll
    for (int i = 0; i < 8; i++) {
        int idx = tid + i * 256;              // 0..2047
        int rr = idx >> 4;                    // hw row 0..127
        int uc = idx & 15;                    // u32 col (2 c each)
        __nv_bfloat16 h0 = sh[2 * uc][rr],   h1 = sh[2 * uc + 1][rr];
        __nv_bfloat16 l0 = sl[2 * uc][rr],   l1 = sl[2 * uc + 1][rr];
        uint32_t ph = ((uint32_t)__bfloat16_as_ushort(h1) << 16) | __bfloat16_as_ushort(h0);
        uint32_t pl = ((uint32_t)__bfloat16_as_ushort(l1) << 16) | __bfloat16_as_ushort(l0);
        size_t off = ((size_t)b * NHW + hw_t * 128 + rr) * NC + c_t * 32 + 2 * uc;
        *(uint32_t*)(g_HT + off) = ph;
        *(uint32_t*)(g_LT + off) = pl;
    }
}

// ---------------------------------------------------------------------------
// mma.sync GEMM: D = Ah*Bh^T + Ah*Bl^T + Al*Bh^T   (128x128 tile, BK=16)
// static smem 48KB: 2 stages x 4 operands x 128 rows x 48B (conflict-free).
// MODE 0: Gram (K=4096, triangle+mirror, writes Gh/Gl = G/64)
// MODE 1: energy (K=512, E = D + bias*s64)
// MODE 2: out    (K=512, out = D + bias)
// ---------------------------------------------------------------------------
#define ROW_B    48
#define OP_B     (128 * ROW_B)      // 6144 bytes per operand tile
#define STAGE_B  (4 * OP_B)         // 24576
// total static: 2 * STAGE_B = 49152 = 48KB exactly

__device__ __forceinline__ void load_stage(uint32_t sb, int tid, int s, int k0,
                                           const __nv_bfloat16* Ah, const __nv_bfloat16* Al,
                                           const __nv_bfloat16* Bh, const __nv_bfloat16* Bl,
                                           int lda, int ldb) {
    uint32_t st = sb + s * STAGE_B;
    int r = tid >> 1, q = tid & 1;            // row 0..127, 16B chunk 0..1
    uint32_t so = r * ROW_B + q * 16;
    size_t  go = (size_t)r * lda + k0 + q * 8;
    size_t  gob = (size_t)r * ldb + k0 + q * 8;
    CP_ASYNC16(st + so,             Ah + go);
    CP_ASYNC16(st + OP_B + so,      Al + go);
    CP_ASYNC16(st + 2 * OP_B + so,  Bh + gob);
    CP_ASYNC16(st + 3 * OP_B + so,  Bl + gob);
    CP_COMMIT();
}

template <int MODE>
__global__ __launch_bounds__(256) void mma_kernel(const float* __restrict__ bias,
                                                  float* __restrict__ outp) {
    __shared__ __align__(16) char smem[2 * STAGE_B];
    uint32_t sb = smem_to_u32(smem);
    int tid = threadIdx.x, wid = tid >> 5, lane = tid & 31;

    int b, K, lda, ldb;
    int bi = 0, bj = 0, bm = 0, bn = 0;
    const __nv_bfloat16 *Ah, *Al, *Bh, *Bl;
    if (MODE == 0) {
        const int TI[10] = {0,0,0,0,1,1,1,2,2,3};
        const int TJ[10] = {0,1,2,3,1,2,3,2,3,3};
        b = blockIdx.x / 10;
        int tri = blockIdx.x % 10;
        bi = TI[tri]; bj = TJ[tri];
        Ah = g_H + ((size_t)b * NC + bi * 128) * NHW;
        Al = g_L + ((size_t)b * NC + bi * 128) * NHW;
        Bh = g_H + ((size_t)b * NC + bj * 128) * NHW;
        Bl = g_L + ((size_t)b * NC + bj * 128) * NHW;
        lda = NHW; ldb = NHW; K = NHW;
    } else if (MODE == 1) {
        b = blockIdx.x >> 3;
        int t = blockIdx.x & 7; bm = t >> 2; bn = t & 3;
        Ah = g_Wh + (size_t)(bm * 128) * NC;
        Al = g_Wl + (size_t)(bm * 128) * NC;
        Bh = g_Gh + ((size_t)b * NC + bn * 128) * NC;
        Bl = g_Gl + ((size_t)b * NC + bn * 128) * NC;
        lda = NC; ldb = NC; K = NC;
    } else {
        b = blockIdx.x >> 6;
        int t = blockIdx.x & 63; bm = t >> 5; bn = t & 31;
        Ah = g_Mh + ((size_t)b * NC1 + bm * 128) * NC;
        Al = g_Ml + ((size_t)b * NC1 + bm * 128) * NC;
        Bh = g_HT + ((size_t)b * NHW + bn * 128) * NC;
        Bl = g_LT + ((size_t)b * NHW + bn * 128) * NC;
        lda = NC; ldb = NC; K = NC;
    }

    int mw = (wid >> 1) * 32;     // warp M offset (4 warps in M)
    int nw = (wid & 1) * 64;      // warp N offset (2 warps in N)

    float acc[2][8][4];
#pragma unroll
    for (int mt = 0; mt < 2; mt++)
#pragma unroll
        for (int nt = 0; nt < 8; nt++)
#pragma unroll
            for (int k = 0; k < 4; k++) acc[mt][nt][k] = 0.f;

    // ldmatrix lane address components
    int a_r  = lane & 15;                        // A row within m16
    int a_c  = (lane >> 4) & 1;                  // A k8 chunk select
    int b_r  = (lane & 7) + ((lane >> 4) << 3);  // B n row within n16
    int b_c  = (lane >> 3) & 1;                  // B k8 chunk select

    int NCH = K >> 4;                            // BK=16 iterations
    load_stage(sb, tid, 0, 0,  Ah, Al, Bh, Bl, lda, ldb);
    load_stage(sb, tid, 1, 16, Ah, Al, Bh, Bl, lda, ldb);

    for (int c = 0; c < NCH; c++) {
        int s = c & 1;
        if (c < NCH - 1) CP_WAIT1(); else CP_WAIT0();
        __syncthreads();
        uint32_t st = sb + s * STAGE_B;
        uint32_t ah[2][4], al[2][4];
#pragma unroll
        for (int mt = 0; mt < 2; mt++) {
            uint32_t ao = (mw + mt * 16 + a_r) * ROW_B + a_c * 16;
            LDMX4(ah[mt], st + ao);
            LDMX4(al[mt], st + OP_B + ao);
        }
#pragma unroll
        for (int ntp = 0; ntp < 4; ntp++) {
            uint32_t bh[4], bl[4];
            uint32_t bo = (nw + ntp * 16 + b_r) * ROW_B + b_c * 16;
            LDMX4(bh, st + 2 * OP_B + bo);
            LDMX4(bl, st + 3 * OP_B + bo);
#pragma unroll
            for (int mt = 0; mt < 2; mt++) {
#pragma unroll
                for (int h = 0; h < 2; h++) {
                    int nt = ntp * 2 + h;
                    MMA_BF16(acc[mt][nt], ah[mt], bh[2*h], bh[2*h+1]);
                    MMA_BF16(acc[mt][nt], al[mt], bh[2*h], bh[2*h+1]);
                    MMA_BF16(acc[mt][nt], ah[mt], bl[2*h], bl[2*h+1]);
                }
            }
        }
        __syncthreads();
        if (c + 2 < NCH) load_stage(sb, tid, s, (c + 2) * 16, Ah, Al, Bh, Bl, lda, ldb);
    }

    // ---- epilogue ----
    int g  = lane >> 2;         // row in m16 frag (plus +8 for regs 2,3)
    int tg = (lane & 3) * 2;    // col pair base in n8 frag

    if (MODE == 0) {
        size_t gb = (size_t)b * NC * NC;
        const float inv = 0.015625f;
#pragma unroll
        for (int mt = 0; mt < 2; mt++) {
#pragma unroll
            for (int nt = 0; nt < 8; nt++) {
#pragma unroll
                for (int half = 0; half < 2; half++) {
                    int row = bi * 128 + mw + mt * 16 + g + half * 8;
                    int col = bj * 128 + nw + nt * 8 + tg;
                    float v0 = acc[mt][nt][2 * half]     * inv;
                    float v1 = acc[mt][nt][2 * half + 1] * inv;
                    __nv_bfloat16 h0 = __float2bfloat16(v0), h1 = __float2bfloat16(v1);
                    __nv_bfloat16 l0 = __float2bfloat16(v0 - __bfloat162float(h0));
                    __nv_bfloat16 l1 = __float2bfloat16(v1 - __bfloat162float(h1));
                    *(uint32_t*)(g_Gh + gb + (size_t)row * NC + col) =
                        ((uint32_t)__bfloat16_as_ushort(h1) << 16) | __bfloat16_as_ushort(h0);
                    *(uint32_t*)(g_Gl + gb + (size_t)row * NC + col) =
                        ((uint32_t)__bfloat16_as_ushort(l1) << 16) | __bfloat16_as_ushort(l0);
                    if (bi != bj) {
                        g_Gh[gb + (size_t)col * NC + row] = h0;
                        g_Gl[gb + (size_t)col * NC + row] = l0;
                        g_Gh[gb + (size_t)(col + 1) * NC + row] = h1;
                        g_Gl[gb + (size_t)(col + 1) * NC + row] = l1;
                    }
                }
            }
        }
    } else if (MODE == 1) {
#pragma unroll
        for (int mt = 0; mt < 2; mt++) {
#pragma unroll
            for (int half = 0; half < 2; half++) {
                int q = bm * 128 + mw + mt * 16 + g + half * 8;
                float bq = bias[q];
                float* dst = g_E + ((size_t)b * NC1 + q) * NC;
#pragma unroll
                for (int nt = 0; nt < 8; nt++) {
                    int col = bn * 128 + nw + nt * 8 + tg;
                    float2 sv = *(const float2*)(g_s + b * NC + col);
                    float2 o;
                    o.x = acc[mt][nt][2 * half]     + bq * sv.x;
                    o.y = acc[mt][nt][2 * half + 1] + bq * sv.y;
                    *(float2*)(dst + col) = o;
                }
            }
        }
    } else {
#pragma unroll
        for (int mt = 0; mt < 2; mt++) {
#pragma unroll
            for (int half = 0; half < 2; half++) {
                int q = bm * 128 + mw + mt * 16 + g + half * 8;
                float bq = bias[q];
                float* dst = outp + ((size_t)b * NC1 + q) * NHW + bn * 128;
#pragma unroll
                for (int nt = 0; nt < 8; nt++) {
                    int col = nw + nt * 8 + tg;
                    float2 o;
                    o.x = acc[mt][nt][2 * half]     + bq;
                    o.y = acc[mt][nt][2 * half + 1] + bq;
                    *(float2*)(dst + col) = o;
                }
            }
        }
    }
}

// ---------------------------------------------------------------------------
// softmax: M = gamma * softmax(E, axis=-1) + W, split to bf16 hi/lo
// ---------------------------------------------------------------------------
__global__ void softmax_kernel(const float* __restrict__ W,
                               const float* __restrict__ gamma) {
    int bid = blockIdx.x;             // b*256 + q
    int q = bid & 255;
    int t = threadIdx.x;              // 128
    const float* Er = g_E + (size_t)bid * NC;
    float e[4];
#pragma unroll
    for (int i = 0; i < 4; i++) e[i] = Er[t + i * 128];
    float mx = fmaxf(fmaxf(e[0], e[1]), fmaxf(e[2], e[3]));

    __shared__ float red[128];
    red[t] = mx; __syncthreads();
    for (int s = 64; s > 0; s >>= 1) { if (t < s) red[t] = fmaxf(red[t], red[t + s]); __syncthreads(); }
    mx = red[0];
    __syncthreads();

    float p[4], sum = 0.f;
#pragma unroll
    for (int i = 0; i < 4; i++) { p[i] = __expf(e[i] - mx); sum += p[i]; }
    red[t] = sum; __syncthreads();
    for (int s = 64; s > 0; s >>= 1) { if (t < s) red[t] += red[t + s]; __syncthreads(); }
    sum = red[0];

    float scale = gamma[0] / sum;
    const float* Wr = W + (size_t)q * NC;
    __nv_bfloat16* Mh = g_Mh + (size_t)bid * NC;
    __nv_bfloat16* Ml = g_Ml + (size_t)bid * NC;
#pragma unroll
    for (int i = 0; i < 4; i++) {
        float v = p[i] * scale + Wr[t + i * 128];
        __nv_bfloat16 h = __float2bfloat16(v);
        Mh[t + i * 128] = h;
        Ml[t + i * 128] = __float2bfloat16(v - __bfloat162float(h));
    }
}

// ---------------------------------------------------------------------------
extern "C" void kernel_launch(void* const* d_in, const int* in_sizes, int n_in,
                              void* d_out, int out_size) {
    const float *x = nullptr, *w = nullptr, *bias = nullptr, *gamma = nullptr;
    for (int i = 0; i < n_in; i++) {
        switch (in_sizes[i]) {
            case NB * NC * NHW: x     = (const float*)d_in[i]; break;
            case NC1 * NC:      w     = (const float*)d_in[i]; break;
            case NC1:           bias  = (const float*)d_in[i]; break;
            case 1:             gamma = (const float*)d_in[i]; break;
        }
    }
    if (!x)     x     = (const float*)d_in[0];
    if (!w)     w     = (const float*)d_in[1];
    if (!bias)  bias  = (const float*)d_in[2];
    if (!gamma) gamma = (const float*)d_in[3];
    float* out = (float*)d_out;

    wsplit_kernel  <<<128, 256>>>(w);
    rowsum_kernel  <<<NB * NC, 128>>>(x);
    convert_kernel <<<NB * 16 * 32, 256>>>(x);
    mma_kernel<0>  <<<NB * 10, 256>>>(bias, nullptr);   // Gram
    mma_kernel<1>  <<<NB * 8, 256>>>(bias, nullptr);    // energy
    softmax_kernel <<<NB * NC1, 128>>>(w, gamma);
    mma_kernel<2>  <<<NB * 64, 256>>>(bias, out);       // out
}

// round 8
// speedup vs baseline: 2.0467x; 1.2803x over previous
#include <cuda_runtime.h>
#include <cuda_bf16.h>
#include <cstdint>

#define NB   16
#define NC   512
#define NC1  256
#define NHW  4096

// ---------------- scratch (device globals; no allocation allowed) ----------
__device__ __nv_bfloat16 g_H [(size_t)NB * NC  * NHW];  // x hi, [b][c][hw]
__device__ __nv_bfloat16 g_L [(size_t)NB * NC  * NHW];  // x lo
__device__ __nv_bfloat16 g_HT[(size_t)NB * NHW * NC ];  // x hi, [b][hw][c]
__device__ __nv_bfloat16 g_LT[(size_t)NB * NHW * NC ];  // x lo transposed
__device__ float         g_Gp[4ull * NB * NC * NC];     // split-K Gram partials (67MB)
__device__ __nv_bfloat16 g_Gh[(size_t)NB * NC  * NC ];  // (Gram/64) hi
__device__ __nv_bfloat16 g_Gl[(size_t)NB * NC  * NC ];  // (Gram/64) lo
__device__ float         g_E [(size_t)NB * NC1 * NC ];  // energy
__device__ __nv_bfloat16 g_Mh[(size_t)NB * NC1 * NC ];  // (gamma*attn+W) hi
__device__ __nv_bfloat16 g_Ml[(size_t)NB * NC1 * NC ];
__device__ __nv_bfloat16 g_Wh[NC1 * NC];
__device__ __nv_bfloat16 g_Wl[NC1 * NC];
__device__ float         g_s [NB * NC];                 // rowsum(x)/64

// ---------------- PTX helpers ----------------------------------------------
__device__ __forceinline__ uint32_t smem_to_u32(const void* p) {
    uint32_t a;
    asm("{ .reg .u64 t; cvta.to.shared.u64 t, %1; cvt.u32.u64 %0, t; }" : "=r"(a) : "l"(p));
    return a;
}
#define CP_ASYNC16(dst, src) \
    asm volatile("cp.async.cg.shared.global [%0], [%1], 16;" :: "r"(dst), "l"(src) : "memory")
#define CP_COMMIT() asm volatile("cp.async.commit_group;" ::: "memory")
#define CP_WAIT1()  asm volatile("cp.async.wait_group 1;" ::: "memory")
#define CP_WAIT0()  asm volatile("cp.async.wait_group 0;" ::: "memory")

#define LDMX4(r, addr) \
    asm volatile("ldmatrix.sync.aligned.m8n8.x4.shared.b16 {%0,%1,%2,%3}, [%4];" \
                 : "=r"((r)[0]), "=r"((r)[1]), "=r"((r)[2]), "=r"((r)[3]) : "r"(addr))

#define MMA_BF16(d, a, b0, b1) \
    asm volatile("mma.sync.aligned.m16n8k16.row.col.f32.bf16.bf16.f32 " \
                 "{%0,%1,%2,%3}, {%4,%5,%6,%7}, {%8,%9}, {%0,%1,%2,%3};" \
                 : "+f"((d)[0]), "+f"((d)[1]), "+f"((d)[2]), "+f"((d)[3]) \
                 : "r"((a)[0]), "r"((a)[1]), "r"((a)[2]), "r"((a)[3]), "r"(b0), "r"(b1))

// ---------------------------------------------------------------------------
// prep kernels
// ---------------------------------------------------------------------------
__global__ void wsplit_kernel(const float* __restrict__ w) {
    int i = blockIdx.x * 256 + threadIdx.x;
#pragma unroll
    for (int j = 0; j < 4; j++) {
        int idx = i * 4 + j;
        float v = w[idx];
        __nv_bfloat16 h = __float2bfloat16(v);
        g_Wh[idx] = h;
        g_Wl[idx] = __float2bfloat16(v - __bfloat162float(h));
    }
}

__global__ void rowsum_kernel(const float* __restrict__ x) {
    int row = blockIdx.x;                            // b*512 + c
    int t = threadIdx.x;                             // 128
    const float4* xr = (const float4*)(x + (size_t)row * NHW);
    float sum = 0.f;
#pragma unroll
    for (int i = 0; i < 8; i++) {
        float4 v = xr[i * 128 + t];
        sum += (v.x + v.y) + (v.z + v.w);
    }
    __shared__ float red[128];
    red[t] = sum; __syncthreads();
    for (int s = 64; s > 0; s >>= 1) { if (t < s) red[t] += red[t + s]; __syncthreads(); }
    if (t == 0) g_s[row] = red[0] * 0.015625f;
}

// x -> H/L ([b][c][hw]) and HT/LT ([b][hw][c]); tiles 32c x 128hw
__global__ __launch_bounds__(256) void convert_kernel(const float* __restrict__ x) {
    int bx = blockIdx.x;
    int hw_t = bx & 31;
    int c_t  = (bx >> 5) & 15;
    int b    = bx >> 9;
    int tid = threadIdx.x;
    const float* xp = x + ((size_t)b * NC + c_t * 32) * NHW + hw_t * 128;

    __shared__ __nv_bfloat16 sh[32][136];
    __shared__ __nv_bfloat16 sl[32][136];

#pragma unroll
    for (int i = 0; i < 16; i++) {
        int idx = tid + i * 256;
        int r = idx >> 7, col = idx & 127;
        float v = xp[(size_t)r * NHW + col];
        __nv_bfloat16 h = __float2bfloat16(v);
        __nv_bfloat16 l = __float2bfloat16(v - __bfloat162float(h));
        size_t go = ((size_t)b * NC + c_t * 32 + r) * NHW + hw_t * 128 + col;
        g_H[go] = h; g_L[go] = l;
        sh[r][col] = h; sl[r][col] = l;
    }
    __syncthreads();
#pragma unroll
    for (int i = 0; i < 8; i++) {
        int idx = tid + i * 256;              // 0..2047
        int rr = idx >> 4;                    // hw row 0..127
        int uc = idx & 15;                    // u32 col (2 c each)
        __nv_bfloat16 h0 = sh[2 * uc][rr],   h1 = sh[2 * uc + 1][rr];
        __nv_bfloat16 l0 = sl[2 * uc][rr],   l1 = sl[2 * uc + 1][rr];
        uint32_t ph = ((uint32_t)__bfloat16_as_ushort(h1) << 16) | __bfloat16_as_ushort(h0);
        uint32_t pl = ((uint32_t)__bfloat16_as_ushort(l1) << 16) | __bfloat16_as_ushort(l0);
        size_t off = ((size_t)b * NHW + hw_t * 128 + rr) * NC + c_t * 32 + 2 * uc;
        *(uint32_t*)(g_HT + off) = ph;
        *(uint32_t*)(g_LT + off) = pl;
    }
}

// ---------------------------------------------------------------------------
// mma.sync GEMM: D = Ah*Bh^T + Ah*Bl^T + Al*Bh^T   (128x128 tile, BK=16)
// static smem 48KB, 2-stage cp.async, term-major MMA ordering (dep dist 4).
// MODE 0: Gram split-K (K=1024/block, 4 splits), fp32 partials + mirror
// MODE 1: energy (K=512, E = D + bias*s64)
// MODE 2: out    (K=512, out = D + bias)
// ---------------------------------------------------------------------------
#define ROW_B    48
#define OP_B     (128 * ROW_B)      // 6144 bytes per operand tile
#define STAGE_B  (4 * OP_B)         // 24576

__device__ __forceinline__ void load_stage(uint32_t sb, int tid, int s, int k0,
                                           const __nv_bfloat16* Ah, const __nv_bfloat16* Al,
                                           const __nv_bfloat16* Bh, const __nv_bfloat16* Bl,
                                           int lda, int ldb) {
    uint32_t st = sb + s * STAGE_B;
    int r = tid >> 1, q = tid & 1;            // row 0..127, 16B chunk 0..1
    uint32_t so = r * ROW_B + q * 16;
    size_t  go  = (size_t)r * lda + k0 + q * 8;
    size_t  gob = (size_t)r * ldb + k0 + q * 8;
    CP_ASYNC16(st + so,             Ah + go);
    CP_ASYNC16(st + OP_B + so,      Al + go);
    CP_ASYNC16(st + 2 * OP_B + so,  Bh + gob);
    CP_ASYNC16(st + 3 * OP_B + so,  Bl + gob);
    CP_COMMIT();
}

template <int MODE>
__global__ __launch_bounds__(256) void mma_kernel(const float* __restrict__ bias,
                                                  float* __restrict__ outp) {
    __shared__ __align__(16) char smem[2 * STAGE_B];
    uint32_t sb = smem_to_u32(smem);
    int tid = threadIdx.x, wid = tid >> 5, lane = tid & 31;

    int b, K, lda, ldb;
    int bi = 0, bj = 0, bm = 0, bn = 0, kc = 0;
    const __nv_bfloat16 *Ah, *Al, *Bh, *Bl;
    if (MODE == 0) {
        const int TI[10] = {0,0,0,0,1,1,1,2,2,3};
        const int TJ[10] = {0,1,2,3,1,2,3,2,3,3};
        kc = blockIdx.x & 3;                   // split-K index
        int t2 = blockIdx.x >> 2;
        b = t2 / 10;
        int tri = t2 % 10;
        bi = TI[tri]; bj = TJ[tri];
        Ah = g_H + ((size_t)b * NC + bi * 128) * NHW + kc * 1024;
        Al = g_L + ((size_t)b * NC + bi * 128) * NHW + kc * 1024;
        Bh = g_H + ((size_t)b * NC + bj * 128) * NHW + kc * 1024;
        Bl = g_L + ((size_t)b * NC + bj * 128) * NHW + kc * 1024;
        lda = NHW; ldb = NHW; K = 1024;
    } else if (MODE == 1) {
        b = blockIdx.x >> 3;
        int t = blockIdx.x & 7; bm = t >> 2; bn = t & 3;
        Ah = g_Wh + (size_t)(bm * 128) * NC;
        Al = g_Wl + (size_t)(bm * 128) * NC;
        Bh = g_Gh + ((size_t)b * NC + bn * 128) * NC;
        Bl = g_Gl + ((size_t)b * NC + bn * 128) * NC;
        lda = NC; ldb = NC; K = NC;
    } else {
        b = blockIdx.x >> 6;
        int t = blockIdx.x & 63; bm = t >> 5; bn = t & 31;
        Ah = g_Mh + ((size_t)b * NC1 + bm * 128) * NC;
        Al = g_Ml + ((size_t)b * NC1 + bm * 128) * NC;
        Bh = g_HT + ((size_t)b * NHW + bn * 128) * NC;
        Bl = g_LT + ((size_t)b * NHW + bn * 128) * NC;
        lda = NC; ldb = NC; K = NC;
    }

    int mw = (wid >> 1) * 32;     // warp M offset (4 warps in M)
    int nw = (wid & 1) * 64;      // warp N offset (2 warps in N)

    float acc[2][8][4];
#pragma unroll
    for (int mt = 0; mt < 2; mt++)
#pragma unroll
        for (int nt = 0; nt < 8; nt++)
#pragma unroll
            for (int k = 0; k < 4; k++) acc[mt][nt][k] = 0.f;

    // ldmatrix lane address components
    int a_r  = lane & 15;                        // A row within m16
    int a_c  = (lane >> 4) & 1;                  // A k8 chunk select
    int b_r  = (lane & 7) + ((lane >> 4) << 3);  // B n row within n16
    int b_c  = (lane >> 3) & 1;                  // B k8 chunk select

    int NCH = K >> 4;                            // BK=16 iterations
    load_stage(sb, tid, 0, 0,  Ah, Al, Bh, Bl, lda, ldb);
    load_stage(sb, tid, 1, 16, Ah, Al, Bh, Bl, lda, ldb);

    for (int c = 0; c < NCH; c++) {
        int s = c & 1;
        if (c < NCH - 1) CP_WAIT1(); else CP_WAIT0();
        __syncthreads();
        uint32_t st = sb + s * STAGE_B;
        uint32_t ah[2][4], al[2][4];
#pragma unroll
        for (int mt = 0; mt < 2; mt++) {
            uint32_t ao = (mw + mt * 16 + a_r) * ROW_B + a_c * 16;
            LDMX4(ah[mt], st + ao);
            LDMX4(al[mt], st + OP_B + ao);
        }
#pragma unroll
        for (int ntp = 0; ntp < 4; ntp++) {
            uint32_t bh[4], bl[4];
            uint32_t bo = (nw + ntp * 16 + b_r) * ROW_B + b_c * 16;
            LDMX4(bh, st + 2 * OP_B + bo);
            LDMX4(bl, st + 3 * OP_B + bo);
            // term-major ordering: 4 independent MMAs per term pass (dep dist 4)
#pragma unroll
            for (int mt = 0; mt < 2; mt++)
#pragma unroll
                for (int h = 0; h < 2; h++)
                    MMA_BF16(acc[mt][ntp * 2 + h], ah[mt], bh[2*h], bh[2*h+1]);
#pragma unroll
            for (int mt = 0; mt < 2; mt++)
#pragma unroll
                for (int h = 0; h < 2; h++)
                    MMA_BF16(acc[mt][ntp * 2 + h], al[mt], bh[2*h], bh[2*h+1]);
#pragma unroll
            for (int mt = 0; mt < 2; mt++)
#pragma unroll
                for (int h = 0; h < 2; h++)
                    MMA_BF16(acc[mt][ntp * 2 + h], ah[mt], bl[2*h], bl[2*h+1]);
        }
        __syncthreads();
        if (c + 2 < NCH) load_stage(sb, tid, s, (c + 2) * 16, Ah, Al, Bh, Bl, lda, ldb);
    }

    // ---- epilogue ----
    int g  = lane >> 2;         // row in m16 frag (plus +8 for regs 2,3)
    int tg = (lane & 3) * 2;    // col pair base in n8 frag

    if (MODE == 0) {
        float* Gp = g_Gp + ((size_t)kc * NB + b) * NC * NC;
#pragma unroll
        for (int mt = 0; mt < 2; mt++) {
#pragma unroll
            for (int nt = 0; nt < 8; nt++) {
#pragma unroll
                for (int half = 0; half < 2; half++) {
                    int row = bi * 128 + mw + mt * 16 + g + half * 8;
                    int col = bj * 128 + nw + nt * 8 + tg;
                    float v0 = acc[mt][nt][2 * half];
                    float v1 = acc[mt][nt][2 * half + 1];
                    *(float2*)(Gp + (size_t)row * NC + col) = make_float2(v0, v1);
                    if (bi != bj) {
                        Gp[(size_t)col * NC + row]       = v0;
                        Gp[(size_t)(col + 1) * NC + row] = v1;
                    }
                }
            }
        }
    } else if (MODE == 1) {
#pragma unroll
        for (int mt = 0; mt < 2; mt++) {
#pragma unroll
            for (int half = 0; half < 2; half++) {
                int q = bm * 128 + mw + mt * 16 + g + half * 8;
                float bq = bias[q];
                float* dst = g_E + ((size_t)b * NC1 + q) * NC;
#pragma unroll
                for (int nt = 0; nt < 8; nt++) {
                    int col = bn * 128 + nw + nt * 8 + tg;
                    float2 sv = *(const float2*)(g_s + b * NC + col);
                    float2 o;
                    o.x = acc[mt][nt][2 * half]     + bq * sv.x;
                    o.y = acc[mt][nt][2 * half + 1] + bq * sv.y;
                    *(float2*)(dst + col) = o;
                }
            }
        }
    } else {
#pragma unroll
        for (int mt = 0; mt < 2; mt++) {
#pragma unroll
            for (int half = 0; half < 2; half++) {
                int q = bm * 128 + mw + mt * 16 + g + half * 8;
                float bq = bias[q];
                float* dst = outp + ((size_t)b * NC1 + q) * NHW + bn * 128;
#pragma unroll
                for (int nt = 0; nt < 8; nt++) {
                    int col = nw + nt * 8 + tg;
                    float2 o;
                    o.x = acc[mt][nt][2 * half]     + bq;
                    o.y = acc[mt][nt][2 * half + 1] + bq;
                    *(float2*)(dst + col) = o;
                }
            }
        }
    }
}

// ---------------------------------------------------------------------------
// Reduce 4 K-split Gram partials -> Gh/Gl = (sum/64) split to bf16 hi/lo
// ---------------------------------------------------------------------------
__global__ void greduce_kernel() {
    int idx = blockIdx.x * 256 + threadIdx.x;     // 0..1048575 float4s
    const size_t per = (size_t)NB * NC * NC / 4;  // float4s per partial
    const float4* p = (const float4*)g_Gp;
    float4 a = p[idx], b2 = p[per + idx], c = p[2 * per + idx], d = p[3 * per + idx];
    const float inv = 0.015625f;
    float v[4];
    v[0] = ((a.x + b2.x) + (c.x + d.x)) * inv;
    v[1] = ((a.y + b2.y) + (c.y + d.y)) * inv;
    v[2] = ((a.z + b2.z) + (c.z + d.z)) * inv;
    v[3] = ((a.w + b2.w) + (c.w + d.w)) * inv;
    uint32_t ph[2], pl[2];
#pragma unroll
    for (int k = 0; k < 2; k++) {
        __nv_bfloat16 h0 = __float2bfloat16(v[2*k]),   h1 = __float2bfloat16(v[2*k+1]);
        __nv_bfloat16 l0 = __float2bfloat16(v[2*k]   - __bfloat162float(h0));
        __nv_bfloat16 l1 = __float2bfloat16(v[2*k+1] - __bfloat162float(h1));
        ph[k] = ((uint32_t)__bfloat16_as_ushort(h1) << 16) | __bfloat16_as_ushort(h0);
        pl[k] = ((uint32_t)__bfloat16_as_ushort(l1) << 16) | __bfloat16_as_ushort(l0);
    }
    ((uint2*)g_Gh)[idx] = make_uint2(ph[0], ph[1]);
    ((uint2*)g_Gl)[idx] = make_uint2(pl[0], pl[1]);
}

// ---------------------------------------------------------------------------
// softmax: M = gamma * softmax(E, axis=-1) + W, split to bf16 hi/lo
// ---------------------------------------------------------------------------
__global__ void softmax_kernel(const float* __restrict__ W,
                               const float* __restrict__ gamma) {
    int bid = blockIdx.x;             // b*256 + q
    int q = bid & 255;
    int t = threadIdx.x;              // 128
    const float* Er = g_E + (size_t)bid * NC;
    float e[4];
#pragma unroll
    for (int i = 0; i < 4; i++) e[i] = Er[t + i * 128];
    float mx = fmaxf(fmaxf(e[0], e[1]), fmaxf(e[2], e[3]));

    __shared__ float red[128];
    red[t] = mx; __syncthreads();
    for (int s = 64; s > 0; s >>= 1) { if (t < s) red[t] = fmaxf(red[t], red[t + s]); __syncthreads(); }
    mx = red[0];
    __syncthreads();

    float p[4], sum = 0.f;
#pragma unroll
    for (int i = 0; i < 4; i++) { p[i] = __expf(e[i] - mx); sum += p[i]; }
    red[t] = sum; __syncthreads();
    for (int s = 64; s > 0; s >>= 1) { if (t < s) red[t] += red[t + s]; __syncthreads(); }
    sum = red[0];

    float scale = gamma[0] / sum;
    const float* Wr = W + (size_t)q * NC;
    __nv_bfloat16* Mh = g_Mh + (size_t)bid * NC;
    __nv_bfloat16* Ml = g_Ml + (size_t)bid * NC;
#pragma unroll
    for (int i = 0; i < 4; i++) {
        float v = p[i] * scale + Wr[t + i * 128];
        __nv_bfloat16 h = __float2bfloat16(v);
        Mh[t + i * 128] = h;
        Ml[t + i * 128] = __float2bfloat16(v - __bfloat162float(h));
    }
}

// ---------------------------------------------------------------------------
extern "C" void kernel_launch(void* const* d_in, const int* in_sizes, int n_in,
                              void* d_out, int out_size) {
    const float *x = nullptr, *w = nullptr, *bias = nullptr, *gamma = nullptr;
    for (int i = 0; i < n_in; i++) {
        switch (in_sizes[i]) {
            case NB * NC * NHW: x     = (const float*)d_in[i]; break;
            case NC1 * NC:      w     = (const float*)d_in[i]; break;
            case NC1:           bias  = (const float*)d_in[i]; break;
            case 1:             gamma = (const float*)d_in[i]; break;
        }
    }
    if (!x)     x     = (const float*)d_in[0];
    if (!w)     w     = (const float*)d_in[1];
    if (!bias)  bias  = (const float*)d_in[2];
    if (!gamma) gamma = (const float*)d_in[3];
    float* out = (float*)d_out;

    wsplit_kernel  <<<128, 256>>>(w);
    rowsum_kernel  <<<NB * NC, 128>>>(x);
    convert_kernel <<<NB * 16 * 32, 256>>>(x);
    mma_kernel<0>  <<<NB * 10 * 4, 256>>>(bias, nullptr);   // Gram split-K
    greduce_kernel <<<4096, 256>>>();
    mma_kernel<1>  <<<NB * 8, 256>>>(bias, nullptr);        // energy
    softmax_kernel <<<NB * NC1, 128>>>(w, gamma);
    mma_kernel<2>  <<<NB * 64, 256>>>(bias, out);           // out
}